// round 8
// baseline (speedup 1.0000x reference)
#include <cuda_runtime.h>
#include <cstdint>
#include <cstddef>

#define BATCH 256
#define SEQ   512
#define INDIM 32
#define H0 64
#define H1 128
#define H2 256

typedef unsigned long long ull;

__device__ float g_pre [(size_t)BATCH * SEQ * 4 * H2];
__device__ float g_x1  [(size_t)BATCH * SEQ * H0];
__device__ float g_x2  [(size_t)BATCH * SEQ * H1];
__device__ float g_x3  [(size_t)BATCH * SEQ * H2];

__device__ __forceinline__ float sigf(float x)  { return 1.f / (1.f + __expf(-x)); }
__device__ __forceinline__ float tanhfast(float x) { return 2.f / (1.f + __expf(-2.f * x)) - 1.f; }

__device__ __forceinline__ void ffma2(ull& d, ull a, ull b) {
    asm("fma.rn.f32x2 %0, %1, %2, %3;" : "=l"(d) : "l"(a), "l"(b), "l"(d));
}
__device__ __forceinline__ ull dup2(float w) {
    ull r; asm("mov.b64 %0, {%1, %1};" : "=l"(r) : "f"(w)); return r;
}
__device__ __forceinline__ ull pack2(float x, float y) {
    ull r; asm("mov.b64 %0, {%1, %2};" : "=l"(r) : "f"(x), "f"(y)); return r;
}
__device__ __forceinline__ void unpk(ull v, float& lo, float& hi) {
    asm("mov.b64 {%0, %1}, %2;" : "=f"(lo), "=f"(hi) : "l"(v));
}
__device__ __forceinline__ uint32_t cvta_s(const void* p) {
    return (uint32_t)__cvta_generic_to_shared(p);
}
__device__ __forceinline__ float lds32(uint32_t a) {
    float v; asm volatile("ld.shared.f32 %0, [%1];" : "=f"(v) : "r"(a)); return v;
}
__device__ __forceinline__ void lds2f32(uint32_t a, float& x, float& y) {
    asm volatile("ld.shared.v2.f32 {%0, %1}, [%2];" : "=f"(x), "=f"(y) : "r"(a));
}
__device__ __forceinline__ void lds2x64(uint32_t a, ull& x, ull& y) {
    asm volatile("ld.shared.v2.u64 {%0, %1}, [%2];" : "=l"(x), "=l"(y) : "r"(a));
}
__device__ __forceinline__ void sts32(uint32_t a, float v) {
    asm volatile("st.shared.f32 [%0], %1;" :: "r"(a), "f"(v));
}
__device__ __forceinline__ void sts64(uint32_t a, ull v) {
    asm volatile("st.shared.b64 [%0], %1;" :: "r"(a), "l"(v));
}
__device__ __forceinline__ void stc64(uint32_t la, unsigned rank, ull v) {
    uint32_t ra;
    asm("mapa.shared::cluster.u32 %0, %1, %2;" : "=r"(ra) : "r"(la), "r"(rank));
    asm volatile("st.shared::cluster.b64 [%0], %1;" :: "r"(ra), "l"(v) : "memory");
}
__device__ __forceinline__ void cluster_arrive_() {
    asm volatile("barrier.cluster.arrive.aligned;" ::: "memory");
}
__device__ __forceinline__ void cluster_wait_() {
    asm volatile("barrier.cluster.wait.aligned;" ::: "memory");
}
__device__ __forceinline__ void cluster_sync_() { cluster_arrive_(); cluster_wait_(); }

// ---------------- input GEMM: C = X @ Wperm^T + bias, m = t*B + b -------------
// Column permutation: output col n holds original gate-row (n&3)*H + (n>>2), so
// pre[t][b] has (i,f,g,o) interleaved per hidden unit -> recurrence loads LDG.128.
// TN: X is indexed [b][t][k] (layer-0 noise layout); else X rows are m-linear.
template <int K, int N, bool TN>
__global__ void __launch_bounds__(256) gemm_pre_kernel(
    const float* __restrict__ X, const float* __restrict__ W,
    const float* __restrict__ bih, const float* __restrict__ bhh,
    float* __restrict__ C)
{
    constexpr int BM = 128, BN = 64, BK = 32;
    constexpr int HN = N / 4;   // hidden size of this layer
    __shared__ float Xs[BK * BM];
    __shared__ float Wt[BK * BN];
    const int m0 = blockIdx.x * BM, n0 = blockIdx.y * BN, tid = threadIdx.x;

    ull acc2[4][4];
#pragma unroll
    for (int p = 0; p < 4; p++)
#pragma unroll
        for (int n = 0; n < 4; n++) acc2[p][n] = 0ull;

    const int tm = (tid >> 4) << 3;
    const int tn = (tid & 15) << 2;
    const uint32_t xsb = cvta_s(Xs);

    for (int k0 = 0; k0 < K; k0 += BK) {
#pragma unroll
        for (int i = 0; i < 4; i++) {
            int f4 = tid + i * 256, row = f4 >> 3, kk = (f4 & 7) << 2;
            size_t src;
            if (TN) {
                const int t = m0 >> 8;              // B=256, BM=128: tile stays in one t
                const int b = (m0 & 255) + row;
                src = ((size_t)b * SEQ + t) * K + k0 + kk;
            } else {
                src = (size_t)(m0 + row) * K + k0 + kk;
            }
            float4 v = *reinterpret_cast<const float4*>(&X[src]);
            Xs[(kk + 0) * BM + row] = v.x; Xs[(kk + 1) * BM + row] = v.y;
            Xs[(kk + 2) * BM + row] = v.z; Xs[(kk + 3) * BM + row] = v.w;
        }
#pragma unroll
        for (int i = 0; i < 2; i++) {
            int f4 = tid + i * 256, row = f4 >> 3, kk = (f4 & 7) << 2;
            const int n = n0 + row;
            const int orow = (n & 3) * HN + (n >> 2);
            float4 v = *reinterpret_cast<const float4*>(&W[(size_t)orow * K + k0 + kk]);
            Wt[(kk + 0) * BN + row] = v.x; Wt[(kk + 1) * BN + row] = v.y;
            Wt[(kk + 2) * BN + row] = v.z; Wt[(kk + 3) * BN + row] = v.w;
        }
        __syncthreads();
#pragma unroll
        for (int kk = 0; kk < BK; kk++) {
            ull a[4];
            lds2x64(xsb + (uint32_t)(kk * BM + tm) * 4u,     a[0], a[1]);
            lds2x64(xsb + (uint32_t)(kk * BM + tm + 4) * 4u, a[2], a[3]);
            float4 b = *reinterpret_cast<const float4*>(&Wt[kk * BN + tn]);
            ull bd[4] = {dup2(b.x), dup2(b.y), dup2(b.z), dup2(b.w)};
#pragma unroll
            for (int p = 0; p < 4; p++)
#pragma unroll
                for (int n = 0; n < 4; n++) ffma2(acc2[p][n], a[p], bd[n]);
        }
        __syncthreads();
    }

    float bb4[4];
#pragma unroll
    for (int nn = 0; nn < 4; nn++) {
        const int n = n0 + tn + nn;
        const int orow = (n & 3) * HN + (n >> 2);
        bb4[nn] = bih[orow] + bhh[orow];
    }
#pragma unroll
    for (int p = 0; p < 4; p++) {
        float e0[4], e1[4];
#pragma unroll
        for (int n = 0; n < 4; n++) unpk(acc2[p][n], e0[n], e1[n]);
        float4 o0 = {e0[0] + bb4[0], e0[1] + bb4[1], e0[2] + bb4[2], e0[3] + bb4[3]};
        float4 o1 = {e1[0] + bb4[0], e1[1] + bb4[1], e1[2] + bb4[2], e1[3] + bb4[3]};
        *reinterpret_cast<float4*>(&C[(size_t)(m0 + tm + 2 * p + 0) * N + n0 + tn]) = o0;
        *reinterpret_cast<float4*>(&C[(size_t)(m0 + tm + 2 * p + 1) * N + n0 + tn]) = o1;
    }
}

// ---------------- LSTM recurrence ---------------------------------------------
// thread = (j, bgrp): unit j (4 gates as f32x2 pairs), BB batches. Per k: one
// LDS.128 weight quad (warp-broadcast) + one v2.f32 h batch-pair => 2 LDS / 8
// FMA-pair-lanes. pre[t][B][4j+g] read as one LDG.128 per batch per step.
// h kept as packed pairs in hs[2][H][NBu] (ull), exchanged via st.shared::cluster.
template <int H, int G, int NB, int BB, int NT>
__global__ void __launch_bounds__(NT) lstm_recur_kernel(
    const float* __restrict__ pre, const float* __restrict__ Whh,
    float* __restrict__ xout)
{
    constexpr int JS   = H / G;
    constexpr int NBGp = NB / BB;
    constexpr int NBu  = NB / 2 + 1;   // padded ull pairs per k-row
    static_assert(JS * NBGp == NT, "map");

    extern __shared__ float sm[];
    float* Ws = sm;                          // [H][JS][4]  (i,f,g,o quad)
    ull*   hs = (ull*)(Ws + H * JS * 4);     // [2][H][NBu]

    const int tid  = threadIdx.x;
    const int bgrp = tid % NBGp;
    const int j    = tid / NBGp;
    const int grp  = (G > 1) ? (blockIdx.x / G) : blockIdx.x;
    const int sl   = (G > 1) ? (blockIdx.x % G) : 0;
    const int b0   = grp * NB;
    const int j0   = sl * JS;

    for (int gj = 0; gj < 4 * JS; gj++) {
        const int g = gj / JS, jj = gj % JS;
        const float* src = Whh + (size_t)(g * H + j0 + jj) * H;
        for (int k = tid; k < H; k += NT)
            Ws[(k * JS + jj) * 4 + g] = src[k];
    }
    for (int i = tid; i < 2 * H * NBu; i += NT) hs[i] = 0ull;
    __syncthreads();
    if (G > 1) cluster_sync_();

    const uint32_t hsb = cvta_s(hs);
    const uint32_t wsb = cvta_s(Ws);

    const int bglob = b0 + bgrp * BB;
    const float* pp[BB];
    float* xo[BB];
    float4 pin[BB];
    float c[BB];
#pragma unroll
    for (int b = 0; b < BB; b++) {
        c[b] = 0.f;
        pp[b] = pre + (size_t)(bglob + b) * 4 * H + (size_t)(j0 + j) * 4;
        xo[b] = xout + (size_t)(bglob + b) * H + (j0 + j);
        pin[b] = __ldcs(reinterpret_cast<const float4*>(pp[b]));   // t = 0
    }

    for (int t = 0; t < SEQ; t++) {
        const uint32_t hba = hsb + (uint32_t)((t & 1) * H * NBu) * 8u;

        ull acc[BB][2];
#pragma unroll
        for (int b = 0; b < BB; b++) {
            acc[b][0] = pack2(pin[b].x, pin[b].y);   // (i,f)
            acc[b][1] = pack2(pin[b].z, pin[b].w);   // (g,o)
        }

#pragma unroll 8
        for (int k = 0; k < H; k++) {
            ull wp0, wp1;
            lds2x64(wsb + (uint32_t)(k * JS + j) * 16u, wp0, wp1);
            if (BB == 2) {
                float h0, h1;
                lds2f32(hba + (uint32_t)(k * NBu + bgrp) * 8u, h0, h1);
                const ull hd0 = dup2(h0), hd1 = dup2(h1);
                ffma2(acc[0][0], hd0, wp0); ffma2(acc[0][1], hd0, wp1);
                ffma2(acc[1][0], hd1, wp0); ffma2(acc[1][1], hd1, wp1);
            } else {
                const float h0 = lds32(hba + (uint32_t)(k * NBu) * 8u + bgrp * 4u);
                const ull hd0 = dup2(h0);
                ffma2(acc[0][0], hd0, wp0); ffma2(acc[0][1], hd0, wp1);
            }
        }

        float hv[BB];
#pragma unroll
        for (int b = 0; b < BB; b++) {
            float si, sf, sg, so;
            unpk(acc[b][0], si, sf);
            unpk(acc[b][1], sg, so);
            c[b] = sigf(sf) * c[b] + sigf(si) * tanhfast(sg);
            hv[b] = sigf(so) * tanhfast(c[b]);
            xo[b][(size_t)t * BATCH * H] = hv[b];
        }

        const uint32_t wba = hsb +
            (uint32_t)((((t + 1) & 1) * H + (j0 + j)) * NBu) * 8u;
        if (BB == 2) {
            const ull hp = pack2(hv[0], hv[1]);
            if (G == 1) {
                sts64(wba + bgrp * 8u, hp);
            } else {
#pragma unroll
                for (unsigned dst = 0; dst < G; dst++) stc64(wba + bgrp * 8u, dst, hp);
            }
        } else {
            sts32(wba + bgrp * 4u, hv[0]);   // G==1 path (layer 0)
        }

        if (G > 1) cluster_arrive_();

        const int tnx = (t + 1 < SEQ) ? t + 1 : t;
#pragma unroll
        for (int b = 0; b < BB; b++)
            pin[b] = __ldcs(reinterpret_cast<const float4*>(
                pp[b] + (size_t)tnx * BATCH * 4 * H));

        if (G > 1) cluster_wait_();
        else       __syncthreads();
    }
}

// ---------------- final linear (OUT_DIM=1) + tanh; x3 is [t][B][H2] -----------
__global__ void __launch_bounds__(256) final_kernel(
    const float* __restrict__ x3, const float* __restrict__ Wl,
    const float* __restrict__ bl, float* __restrict__ out)
{
    int m = (blockIdx.x * 256 + threadIdx.x) >> 5;   // m = t*B + b
    int lane = threadIdx.x & 31;
    const float* xr = x3 + (size_t)m * H2;
    float acc = 0.f;
#pragma unroll
    for (int i = 0; i < 8; i++) acc += xr[i * 32 + lane] * __ldg(&Wl[i * 32 + lane]);
#pragma unroll
    for (int off = 16; off; off >>= 1) acc += __shfl_xor_sync(0xffffffffu, acc, off);
    if (lane == 0) {
        const int t = m >> 8, b = m & 255;
        out[(size_t)b * SEQ + t] = tanhf(acc + bl[0]);
    }
}

// ---------------- launch ----------------
template <typename KernT>
static void launch_cluster(KernT kern, int grid, int nthr, int G, int smem,
                           const float* pre, const float* Whh, float* xout)
{
    cudaLaunchConfig_t cfg = {};
    cfg.gridDim = dim3(grid, 1, 1);
    cfg.blockDim = dim3(nthr, 1, 1);
    cfg.dynamicSmemBytes = smem;
    cfg.stream = 0;
    cudaLaunchAttribute attr[1];
    attr[0].id = cudaLaunchAttributeClusterDimension;
    attr[0].val.clusterDim.x = G;
    attr[0].val.clusterDim.y = 1;
    attr[0].val.clusterDim.z = 1;
    cfg.attrs = attr;
    cfg.numAttrs = 1;
    cudaLaunchKernelEx(&cfg, kern, pre, Whh, xout);
}

extern "C" void kernel_launch(void* const* d_in, const int* in_sizes, int n_in,
                              void* d_out, int out_size)
{
    const float* noise = (const float*)d_in[0];
    const float* Wih0 = (const float*)d_in[1];
    const float* Whh0 = (const float*)d_in[2];
    const float* bih0 = (const float*)d_in[3];
    const float* bhh0 = (const float*)d_in[4];
    const float* Wih1 = (const float*)d_in[5];
    const float* Whh1 = (const float*)d_in[6];
    const float* bih1 = (const float*)d_in[7];
    const float* bhh1 = (const float*)d_in[8];
    const float* Wih2 = (const float*)d_in[9];
    const float* Whh2 = (const float*)d_in[10];
    const float* bih2 = (const float*)d_in[11];
    const float* bhh2 = (const float*)d_in[12];
    const float* Wl   = (const float*)d_in[13];
    const float* bl   = (const float*)d_in[14];
    float* out = (float*)d_out;

    float *pre, *x1, *x2, *x3;
    cudaGetSymbolAddress((void**)&pre, g_pre);
    cudaGetSymbolAddress((void**)&x1,  g_x1);
    cudaGetSymbolAddress((void**)&x2,  g_x2);
    cudaGetSymbolAddress((void**)&x3,  g_x3);

    // smem: Ws[H][JS][4] f32 + hs[2][H][NBu] u64
    const int smem0 = H0 * 64 * 4 * 4 + 2 * H0 * 2 * 8;   //  67,584
    const int smem1 = H1 * 64 * 4 * 4 + 2 * H1 * 3 * 8;   // 137,216
    const int smem2 = H2 * 32 * 4 * 4 + 2 * H2 * 9 * 8;   // 167,936

    cudaFuncSetAttribute(lstm_recur_kernel<H0, 1, 2, 1, 128>,
                         cudaFuncAttributeMaxDynamicSharedMemorySize, smem0);
    cudaFuncSetAttribute(lstm_recur_kernel<H1, 2, 4, 2, 128>,
                         cudaFuncAttributeMaxDynamicSharedMemorySize, smem1);
    cudaFuncSetAttribute(lstm_recur_kernel<H2, 8, 16, 2, 256>,
                         cudaFuncAttributeMaxDynamicSharedMemorySize, smem2);

    const int MBLK = (BATCH * SEQ) / 128;

    gemm_pre_kernel<INDIM, 4 * H0, true><<<dim3(MBLK, (4 * H0) / 64), 256>>>(
        noise, Wih0, bih0, bhh0, pre);
    lstm_recur_kernel<H0, 1, 2, 1, 128><<<128, 128, smem0>>>(pre, Whh0, x1);

    gemm_pre_kernel<H0, 4 * H1, false><<<dim3(MBLK, (4 * H1) / 64), 256>>>(
        x1, Wih1, bih1, bhh1, pre);
    launch_cluster(lstm_recur_kernel<H1, 2, 4, 2, 128>, 128, 128, 2, smem1, pre, Whh1, x2);

    gemm_pre_kernel<H1, 4 * H2, false><<<dim3(MBLK, (4 * H2) / 64), 256>>>(
        x2, Wih2, bih2, bhh2, pre);
    launch_cluster(lstm_recur_kernel<H2, 8, 16, 2, 256>, 128, 256, 8, smem2, pre, Whh2, x3);

    final_kernel<<<(BATCH * SEQ) / 8, 256>>>(x3, Wl, bl, out);
}

// round 10
// speedup vs baseline: 1.2314x; 1.2314x over previous
#include <cuda_runtime.h>
#include <cstdint>
#include <cstddef>

#define BATCH 256
#define SEQ   512
#define INDIM 32
#define H0 64
#define H1 128
#define H2 256

typedef unsigned long long ull;

__device__ float g_pre [(size_t)BATCH * SEQ * 4 * H2];
__device__ float g_x1  [(size_t)BATCH * SEQ * H0];
__device__ float g_x2  [(size_t)BATCH * SEQ * H1];
__device__ float g_x3  [(size_t)BATCH * SEQ * H2];

__device__ __forceinline__ float sigf(float x)  { return 1.f / (1.f + __expf(-x)); }
__device__ __forceinline__ float tanhfast(float x) { return 2.f / (1.f + __expf(-2.f * x)) - 1.f; }

__device__ __forceinline__ void ffma2(ull& d, ull a, ull b) {
    asm("fma.rn.f32x2 %0, %1, %2, %3;" : "=l"(d) : "l"(a), "l"(b), "l"(d));
}
__device__ __forceinline__ ull dup2(float w) {
    ull r; asm("mov.b64 %0, {%1, %1};" : "=l"(r) : "f"(w)); return r;
}
__device__ __forceinline__ ull pack2(float x, float y) {
    ull r; asm("mov.b64 %0, {%1, %2};" : "=l"(r) : "f"(x), "f"(y)); return r;
}
__device__ __forceinline__ void unpk(ull v, float& lo, float& hi) {
    asm("mov.b64 {%0, %1}, %2;" : "=f"(lo), "=f"(hi) : "l"(v));
}
__device__ __forceinline__ uint32_t cvta_s(const void* p) {
    return (uint32_t)__cvta_generic_to_shared(p);
}
__device__ __forceinline__ void stc32(uint32_t la, unsigned rank, float v) {
    uint32_t ra;
    asm("mapa.shared::cluster.u32 %0, %1, %2;" : "=r"(ra) : "r"(la), "r"(rank));
    asm volatile("st.shared::cluster.f32 [%0], %1;" :: "r"(ra), "f"(v) : "memory");
}
__device__ __forceinline__ void stc64(uint32_t la, unsigned rank, ull v) {
    uint32_t ra;
    asm("mapa.shared::cluster.u32 %0, %1, %2;" : "=r"(ra) : "r"(la), "r"(rank));
    asm volatile("st.shared::cluster.b64 [%0], %1;" :: "r"(ra), "l"(v) : "memory");
}
__device__ __forceinline__ void cluster_arrive_() {
    asm volatile("barrier.cluster.arrive.aligned;" ::: "memory");
}
__device__ __forceinline__ void cluster_wait_() {
    asm volatile("barrier.cluster.wait.aligned;" ::: "memory");
}
__device__ __forceinline__ void cluster_sync_() { cluster_arrive_(); cluster_wait_(); }

// ---------------- input GEMM: C = X @ Wperm^T + bias, m = t*B + b -------------
// Output col n holds original gate-row (n&3)*H + (n>>2): pre[t][b] has
// (i,f,g,o) interleaved per hidden unit -> recurrence acc-init is one LDG.128.
// TN: X indexed [b][t][k] (layer-0 noise layout); else rows are m-linear.
template <int K, int N, bool TN>
__global__ void __launch_bounds__(256) gemm_pre_kernel(
    const float* __restrict__ X, const float* __restrict__ W,
    const float* __restrict__ bih, const float* __restrict__ bhh,
    float* __restrict__ C)
{
    constexpr int BM = 128, BN = 64, BK = 32;
    constexpr int HN = N / 4;
    __shared__ float Xs[BK * BM];
    __shared__ float Wt[BK * BN];
    const int m0 = blockIdx.x * BM, n0 = blockIdx.y * BN, tid = threadIdx.x;

    ull acc2[4][4];
#pragma unroll
    for (int p = 0; p < 4; p++)
#pragma unroll
        for (int n = 0; n < 4; n++) acc2[p][n] = 0ull;

    const int tm = (tid >> 4) << 3;
    const int tn = (tid & 15) << 2;

    for (int k0 = 0; k0 < K; k0 += BK) {
#pragma unroll
        for (int i = 0; i < 4; i++) {
            int f4 = tid + i * 256, row = f4 >> 3, kk = (f4 & 7) << 2;
            size_t src;
            if (TN) {
                const int t = m0 >> 8;
                const int b = (m0 & 255) + row;
                src = ((size_t)b * SEQ + t) * K + k0 + kk;
            } else {
                src = (size_t)(m0 + row) * K + k0 + kk;
            }
            float4 v = *reinterpret_cast<const float4*>(&X[src]);
            Xs[(kk + 0) * BM + row] = v.x; Xs[(kk + 1) * BM + row] = v.y;
            Xs[(kk + 2) * BM + row] = v.z; Xs[(kk + 3) * BM + row] = v.w;
        }
#pragma unroll
        for (int i = 0; i < 2; i++) {
            int f4 = tid + i * 256, row = f4 >> 3, kk = (f4 & 7) << 2;
            const int n = n0 + row;
            const int orow = (n & 3) * HN + (n >> 2);
            float4 v = *reinterpret_cast<const float4*>(&W[(size_t)orow * K + k0 + kk]);
            Wt[(kk + 0) * BN + row] = v.x; Wt[(kk + 1) * BN + row] = v.y;
            Wt[(kk + 2) * BN + row] = v.z; Wt[(kk + 3) * BN + row] = v.w;
        }
        __syncthreads();
#pragma unroll
        for (int kk = 0; kk < BK; kk++) {
            float2 a01 = *reinterpret_cast<const float2*>(&Xs[kk * BM + tm + 0]);
            float2 a23 = *reinterpret_cast<const float2*>(&Xs[kk * BM + tm + 2]);
            float2 a45 = *reinterpret_cast<const float2*>(&Xs[kk * BM + tm + 4]);
            float2 a67 = *reinterpret_cast<const float2*>(&Xs[kk * BM + tm + 6]);
            float4 b = *reinterpret_cast<const float4*>(&Wt[kk * BN + tn]);
            ull a[4] = {pack2(a01.x, a01.y), pack2(a23.x, a23.y),
                        pack2(a45.x, a45.y), pack2(a67.x, a67.y)};
            ull bd[4] = {dup2(b.x), dup2(b.y), dup2(b.z), dup2(b.w)};
#pragma unroll
            for (int p = 0; p < 4; p++)
#pragma unroll
                for (int n = 0; n < 4; n++) ffma2(acc2[p][n], a[p], bd[n]);
        }
        __syncthreads();
    }

    float bb4[4];
#pragma unroll
    for (int nn = 0; nn < 4; nn++) {
        const int n = n0 + tn + nn;
        const int orow = (n & 3) * HN + (n >> 2);
        bb4[nn] = bih[orow] + bhh[orow];
    }
#pragma unroll
    for (int p = 0; p < 4; p++) {
        float e0[4], e1[4];
#pragma unroll
        for (int n = 0; n < 4; n++) unpk(acc2[p][n], e0[n], e1[n]);
        float4 o0 = {e0[0] + bb4[0], e0[1] + bb4[1], e0[2] + bb4[2], e0[3] + bb4[3]};
        float4 o1 = {e1[0] + bb4[0], e1[1] + bb4[1], e1[2] + bb4[2], e1[3] + bb4[3]};
        *reinterpret_cast<float4*>(&C[(size_t)(m0 + tm + 2 * p + 0) * N + n0 + tn]) = o0;
        *reinterpret_cast<float4*>(&C[(size_t)(m0 + tm + 2 * p + 1) * N + n0 + tn]) = o1;
    }
}

// ---------------- LSTM recurrence -------------------------------------------
// thread = (j, bgrp): unit j (gate pairs (i,f),(g,o) in f32x2), BB batches.
// Plain (non-volatile) shared loads in 4-k blocks so ptxas can pipeline them.
// h stored as floats hs[2][H][RS] (RS=NB+2 pad), exchanged via st.shared::cluster.
template <int H, int G, int NB, int BB, int NT>
__global__ void __launch_bounds__(NT, 1) lstm_recur_kernel(
    const float* __restrict__ pre, const float* __restrict__ Whh,
    float* __restrict__ xout)
{
    constexpr int JS   = H / G;
    constexpr int NBGp = NB / BB;
    constexpr int RS   = NB + 2;
    static_assert(JS * NBGp == NT, "map");

    extern __shared__ float sm[];
    float* Ws = sm;                          // [H][JS][4]  (i,f,g,o quad)
    float* hs = Ws + H * JS * 4;             // [2][H][RS]

    const int tid  = threadIdx.x;
    const int bgrp = tid % NBGp;
    const int j    = tid / NBGp;
    const int grp  = (G > 1) ? (blockIdx.x / G) : blockIdx.x;
    const int sl   = (G > 1) ? (blockIdx.x % G) : 0;
    const int b0   = grp * NB;
    const int j0   = sl * JS;

    for (int gj = 0; gj < 4 * JS; gj++) {
        const int g = gj / JS, jj = gj % JS;
        const float* src = Whh + (size_t)(g * H + j0 + jj) * H;
        for (int k = tid; k < H; k += NT)
            Ws[(k * JS + jj) * 4 + g] = src[k];
    }
    for (int i = tid; i < 2 * H * RS; i += NT) hs[i] = 0.f;
    __syncthreads();
    if (G > 1) cluster_sync_();

    const int bglob = b0 + bgrp * BB;
    const float* pp[BB];
    float* xo[BB];
    float4 pin[BB];
    float c[BB];
#pragma unroll
    for (int b = 0; b < BB; b++) {
        c[b] = 0.f;
        pp[b] = pre + (size_t)(bglob + b) * 4 * H + (size_t)(j0 + j) * 4;
        xo[b] = xout + (size_t)(bglob + b) * H + (j0 + j);
        pin[b] = __ldcs(reinterpret_cast<const float4*>(pp[b]));   // t = 0
    }

    const float4* wq = reinterpret_cast<const float4*>(Ws) + j;   // stride JS per k

    for (int t = 0; t < SEQ; t++) {
        const float* hrow = hs + (t & 1) * H * RS;

        ull acc[BB][2];
#pragma unroll
        for (int b = 0; b < BB; b++) {
            acc[b][0] = pack2(pin[b].x, pin[b].y);   // (i,f)
            acc[b][1] = pack2(pin[b].z, pin[b].w);   // (g,o)
        }

#pragma unroll 2
        for (int kb = 0; kb < H; kb += 4) {
            float4 w[4];
#pragma unroll
            for (int u = 0; u < 4; u++) w[u] = wq[(kb + u) * JS];
            if (BB == 2) {
                float2 hp[4];
#pragma unroll
                for (int u = 0; u < 4; u++)
                    hp[u] = *reinterpret_cast<const float2*>(
                        &hrow[(kb + u) * RS + bgrp * 2]);
#pragma unroll
                for (int u = 0; u < 4; u++) {
                    const ull wA = pack2(w[u].x, w[u].y);
                    const ull wB = pack2(w[u].z, w[u].w);
                    const ull hd0 = dup2(hp[u].x), hd1 = dup2(hp[u].y);
                    ffma2(acc[0][0], hd0, wA); ffma2(acc[0][1], hd0, wB);
                    ffma2(acc[1][0], hd1, wA); ffma2(acc[1][1], hd1, wB);
                }
            } else {
                float hv[4];
#pragma unroll
                for (int u = 0; u < 4; u++) hv[u] = hrow[(kb + u) * RS + bgrp];
#pragma unroll
                for (int u = 0; u < 4; u++) {
                    const ull wA = pack2(w[u].x, w[u].y);
                    const ull wB = pack2(w[u].z, w[u].w);
                    const ull hd0 = dup2(hv[u]);
                    ffma2(acc[0][0], hd0, wA); ffma2(acc[0][1], hd0, wB);
                }
            }
        }

        float hv[BB];
#pragma unroll
        for (int b = 0; b < BB; b++) {
            float si, sf, sg, so;
            unpk(acc[b][0], si, sf);
            unpk(acc[b][1], sg, so);
            c[b] = sigf(sf) * c[b] + sigf(si) * tanhfast(sg);
            hv[b] = sigf(so) * tanhfast(c[b]);
        }

        // write h for next step (own smem or all cluster peers)
        float* wrow = hs + ((t + 1) & 1) * H * RS + (j0 + j) * RS + bgrp * BB;
        if (G == 1) {
            if (BB == 2) *reinterpret_cast<float2*>(wrow) = make_float2(hv[0], hv[1]);
            else         wrow[0] = hv[0];
        } else {
            const uint32_t la = cvta_s(wrow);
            if (BB == 2) {
                const ull hp = pack2(hv[0], hv[1]);
#pragma unroll
                for (unsigned d = 0; d < G; d++) stc64(la, d, hp);
            } else {
#pragma unroll
                for (unsigned d = 0; d < G; d++) stc32(la, d, hv[0]);
            }
        }

        if (G > 1) cluster_arrive_();

        // hidden under the barrier: xout store + pre(t+1) prefetch
#pragma unroll
        for (int b = 0; b < BB; b++) xo[b][(size_t)t * BATCH * H] = hv[b];
        const int tnx = (t + 1 < SEQ) ? t + 1 : t;
#pragma unroll
        for (int b = 0; b < BB; b++)
            pin[b] = __ldcs(reinterpret_cast<const float4*>(
                pp[b] + (size_t)tnx * BATCH * 4 * H));

        if (G > 1) cluster_wait_();
        else       __syncthreads();
    }
}

// ---------------- final linear (OUT_DIM=1) + tanh; x3 is [t][B][H2] -----------
__global__ void __launch_bounds__(256) final_kernel(
    const float* __restrict__ x3, const float* __restrict__ Wl,
    const float* __restrict__ bl, float* __restrict__ out)
{
    int m = (blockIdx.x * 256 + threadIdx.x) >> 5;   // m = t*B + b
    int lane = threadIdx.x & 31;
    const float* xr = x3 + (size_t)m * H2;
    float acc = 0.f;
#pragma unroll
    for (int i = 0; i < 8; i++) acc += xr[i * 32 + lane] * __ldg(&Wl[i * 32 + lane]);
#pragma unroll
    for (int off = 16; off; off >>= 1) acc += __shfl_xor_sync(0xffffffffu, acc, off);
    if (lane == 0) {
        const int t = m >> 8, b = m & 255;
        out[(size_t)b * SEQ + t] = tanhf(acc + bl[0]);
    }
}

// ---------------- launch ----------------
template <typename KernT>
static void launch_cluster(KernT kern, int grid, int nthr, int G, int smem,
                           const float* pre, const float* Whh, float* xout)
{
    cudaLaunchConfig_t cfg = {};
    cfg.gridDim = dim3(grid, 1, 1);
    cfg.blockDim = dim3(nthr, 1, 1);
    cfg.dynamicSmemBytes = smem;
    cfg.stream = 0;
    cudaLaunchAttribute attr[1];
    attr[0].id = cudaLaunchAttributeClusterDimension;
    attr[0].val.clusterDim.x = G;
    attr[0].val.clusterDim.y = 1;
    attr[0].val.clusterDim.z = 1;
    cfg.attrs = attr;
    cfg.numAttrs = 1;
    cudaLaunchKernelEx(&cfg, kern, pre, Whh, xout);
}

extern "C" void kernel_launch(void* const* d_in, const int* in_sizes, int n_in,
                              void* d_out, int out_size)
{
    const float* noise = (const float*)d_in[0];
    const float* Wih0 = (const float*)d_in[1];
    const float* Whh0 = (const float*)d_in[2];
    const float* bih0 = (const float*)d_in[3];
    const float* bhh0 = (const float*)d_in[4];
    const float* Wih1 = (const float*)d_in[5];
    const float* Whh1 = (const float*)d_in[6];
    const float* bih1 = (const float*)d_in[7];
    const float* bhh1 = (const float*)d_in[8];
    const float* Wih2 = (const float*)d_in[9];
    const float* Whh2 = (const float*)d_in[10];
    const float* bih2 = (const float*)d_in[11];
    const float* bhh2 = (const float*)d_in[12];
    const float* Wl   = (const float*)d_in[13];
    const float* bl   = (const float*)d_in[14];
    float* out = (float*)d_out;

    float *pre, *x1, *x2, *x3;
    cudaGetSymbolAddress((void**)&pre, g_pre);
    cudaGetSymbolAddress((void**)&x1,  g_x1);
    cudaGetSymbolAddress((void**)&x2,  g_x2);
    cudaGetSymbolAddress((void**)&x3,  g_x3);

    // smem: Ws[H][JS][4] + hs[2][H][NB+2] floats
    const int smem0 = (H0 * 64 * 4 + 2 * H0 * 6) * 4;    //  68,608
    const int smem1 = (H1 * 64 * 4 + 2 * H1 * 6) * 4;    // 137,216
    const int smem2 = (H2 * 32 * 4 + 2 * H2 * 18) * 4;   // 167,936

    cudaFuncSetAttribute(lstm_recur_kernel<H0, 1, 4, 1, 256>,
                         cudaFuncAttributeMaxDynamicSharedMemorySize, smem0);
    cudaFuncSetAttribute(lstm_recur_kernel<H1, 2, 4, 1, 256>,
                         cudaFuncAttributeMaxDynamicSharedMemorySize, smem1);
    cudaFuncSetAttribute(lstm_recur_kernel<H2, 8, 16, 2, 256>,
                         cudaFuncAttributeMaxDynamicSharedMemorySize, smem2);

    const int MBLK = (BATCH * SEQ) / 128;

    gemm_pre_kernel<INDIM, 4 * H0, true><<<dim3(MBLK, (4 * H0) / 64), 256>>>(
        noise, Wih0, bih0, bhh0, pre);
    lstm_recur_kernel<H0, 1, 4, 1, 256><<<64, 256, smem0>>>(pre, Whh0, x1);

    gemm_pre_kernel<H0, 4 * H1, false><<<dim3(MBLK, (4 * H1) / 64), 256>>>(
        x1, Wih1, bih1, bhh1, pre);
    launch_cluster(lstm_recur_kernel<H1, 2, 4, 1, 256>, 128, 256, 2, smem1, pre, Whh1, x2);

    gemm_pre_kernel<H1, 4 * H2, false><<<dim3(MBLK, (4 * H2) / 64), 256>>>(
        x2, Wih2, bih2, bhh2, pre);
    launch_cluster(lstm_recur_kernel<H2, 8, 16, 2, 256>, 128, 256, 8, smem2, pre, Whh2, x3);

    final_kernel<<<(BATCH * SEQ) / 8, 256>>>(x3, Wl, bl, out);
}

// round 11
// speedup vs baseline: 1.3141x; 1.0672x over previous
#include <cuda_runtime.h>
#include <cstdint>
#include <cstddef>

#define BATCH 256
#define SEQ   512
#define INDIM 32
#define H0 64
#define H1 128
#define H2 256

typedef unsigned long long ull;

__device__ float g_pre [(size_t)BATCH * SEQ * 4 * H2];
__device__ float g_x1  [(size_t)BATCH * SEQ * H0];
__device__ float g_x2  [(size_t)BATCH * SEQ * H1];
__device__ float g_x3  [(size_t)BATCH * SEQ * H2];

__device__ __forceinline__ float sigf(float x)  { return 1.f / (1.f + __expf(-x)); }
__device__ __forceinline__ float tanhfast(float x) { return 2.f / (1.f + __expf(-2.f * x)) - 1.f; }

__device__ __forceinline__ void ffma2(ull& d, ull a, ull b) {
    asm("fma.rn.f32x2 %0, %1, %2, %3;" : "=l"(d) : "l"(a), "l"(b), "l"(d));
}
__device__ __forceinline__ ull add2(ull a, ull b) {
    ull r; asm("add.rn.f32x2 %0, %1, %2;" : "=l"(r) : "l"(a), "l"(b)); return r;
}
__device__ __forceinline__ ull dup2(float w) {
    ull r; asm("mov.b64 %0, {%1, %1};" : "=l"(r) : "f"(w)); return r;
}
__device__ __forceinline__ ull pack2(float x, float y) {
    ull r; asm("mov.b64 %0, {%1, %2};" : "=l"(r) : "f"(x), "f"(y)); return r;
}
__device__ __forceinline__ void unpk(ull v, float& lo, float& hi) {
    asm("mov.b64 {%0, %1}, %2;" : "=f"(lo), "=f"(hi) : "l"(v));
}
__device__ __forceinline__ uint32_t cvta_s(const void* p) {
    return (uint32_t)__cvta_generic_to_shared(p);
}
__device__ __forceinline__ void stc32(uint32_t la, unsigned rank, float v) {
    uint32_t ra;
    asm("mapa.shared::cluster.u32 %0, %1, %2;" : "=r"(ra) : "r"(la), "r"(rank));
    asm volatile("st.shared::cluster.f32 [%0], %1;" :: "r"(ra), "f"(v) : "memory");
}
__device__ __forceinline__ void stc64(uint32_t la, unsigned rank, ull v) {
    uint32_t ra;
    asm("mapa.shared::cluster.u32 %0, %1, %2;" : "=r"(ra) : "r"(la), "r"(rank));
    asm volatile("st.shared::cluster.b64 [%0], %1;" :: "r"(ra), "l"(v) : "memory");
}
__device__ __forceinline__ void cluster_arrive_() {
    asm volatile("barrier.cluster.arrive.aligned;" ::: "memory");
}
__device__ __forceinline__ void cluster_wait_() {
    asm volatile("barrier.cluster.wait.aligned;" ::: "memory");
}
__device__ __forceinline__ void cluster_sync_() { cluster_arrive_(); cluster_wait_(); }

// ---------------- input GEMM: C = X @ Wperm^T + bias, m = t*B + b -------------
// Output col n = original gate-row (n&3)*H + (n>>2): pre[t][b] has (i,f,g,o)
// interleaved per hidden unit. TN: X indexed [b][t][k] (layer-0 noise).
template <int K, int N, bool TN>
__global__ void __launch_bounds__(256) gemm_pre_kernel(
    const float* __restrict__ X, const float* __restrict__ W,
    const float* __restrict__ bih, const float* __restrict__ bhh,
    float* __restrict__ C)
{
    constexpr int BM = 128, BN = 64, BK = 32;
    constexpr int HN = N / 4;
    __shared__ float Xs[BK * BM];
    __shared__ float Wt[BK * BN];
    const int m0 = blockIdx.x * BM, n0 = blockIdx.y * BN, tid = threadIdx.x;

    ull acc2[4][4];
#pragma unroll
    for (int p = 0; p < 4; p++)
#pragma unroll
        for (int n = 0; n < 4; n++) acc2[p][n] = 0ull;

    const int tm = (tid >> 4) << 3;
    const int tn = (tid & 15) << 2;

    for (int k0 = 0; k0 < K; k0 += BK) {
#pragma unroll
        for (int i = 0; i < 4; i++) {
            int f4 = tid + i * 256, row = f4 >> 3, kk = (f4 & 7) << 2;
            size_t src;
            if (TN) {
                const int t = m0 >> 8;
                const int b = (m0 & 255) + row;
                src = ((size_t)b * SEQ + t) * K + k0 + kk;
            } else {
                src = (size_t)(m0 + row) * K + k0 + kk;
            }
            float4 v = *reinterpret_cast<const float4*>(&X[src]);
            Xs[(kk + 0) * BM + row] = v.x; Xs[(kk + 1) * BM + row] = v.y;
            Xs[(kk + 2) * BM + row] = v.z; Xs[(kk + 3) * BM + row] = v.w;
        }
#pragma unroll
        for (int i = 0; i < 2; i++) {
            int f4 = tid + i * 256, row = f4 >> 3, kk = (f4 & 7) << 2;
            const int n = n0 + row;
            const int orow = (n & 3) * HN + (n >> 2);
            float4 v = *reinterpret_cast<const float4*>(&W[(size_t)orow * K + k0 + kk]);
            Wt[(kk + 0) * BN + row] = v.x; Wt[(kk + 1) * BN + row] = v.y;
            Wt[(kk + 2) * BN + row] = v.z; Wt[(kk + 3) * BN + row] = v.w;
        }
        __syncthreads();
#pragma unroll
        for (int kk = 0; kk < BK; kk++) {
            float2 a01 = *reinterpret_cast<const float2*>(&Xs[kk * BM + tm + 0]);
            float2 a23 = *reinterpret_cast<const float2*>(&Xs[kk * BM + tm + 2]);
            float2 a45 = *reinterpret_cast<const float2*>(&Xs[kk * BM + tm + 4]);
            float2 a67 = *reinterpret_cast<const float2*>(&Xs[kk * BM + tm + 6]);
            float4 b = *reinterpret_cast<const float4*>(&Wt[kk * BN + tn]);
            ull a[4] = {pack2(a01.x, a01.y), pack2(a23.x, a23.y),
                        pack2(a45.x, a45.y), pack2(a67.x, a67.y)};
            ull bd[4] = {dup2(b.x), dup2(b.y), dup2(b.z), dup2(b.w)};
#pragma unroll
            for (int p = 0; p < 4; p++)
#pragma unroll
                for (int n = 0; n < 4; n++) ffma2(acc2[p][n], a[p], bd[n]);
        }
        __syncthreads();
    }

    float bb4[4];
#pragma unroll
    for (int nn = 0; nn < 4; nn++) {
        const int n = n0 + tn + nn;
        const int orow = (n & 3) * HN + (n >> 2);
        bb4[nn] = bih[orow] + bhh[orow];
    }
#pragma unroll
    for (int p = 0; p < 4; p++) {
        float e0[4], e1[4];
#pragma unroll
        for (int n = 0; n < 4; n++) unpk(acc2[p][n], e0[n], e1[n]);
        float4 o0 = {e0[0] + bb4[0], e0[1] + bb4[1], e0[2] + bb4[2], e0[3] + bb4[3]};
        float4 o1 = {e1[0] + bb4[0], e1[1] + bb4[1], e1[2] + bb4[2], e1[3] + bb4[3]};
        *reinterpret_cast<float4*>(&C[(size_t)(m0 + tm + 2 * p + 0) * N + n0 + tn]) = o0;
        *reinterpret_cast<float4*>(&C[(size_t)(m0 + tm + 2 * p + 1) * N + n0 + tn]) = o1;
    }
}

// ---------------- LSTM recurrence: register-resident weights ------------------
// thread = (j, kh): unit j, k-slice [kh*KR, +KR). Weights for all 4 gates of the
// slice live in REGISTERS as (k,k+1) f32x2 pairs. Dot: per batch, KQ broadcast
// LDS.128 of h + 8 FFMA2 each; partial gate sums -> red[] -> one sync ->
// act threads (CPT cells each) sum KH partials + pre (regs), update c (regs),
// write h to all G cluster peers; one cluster barrier per step.
template <int H, int G, int NB, int KH, int CPT>
__global__ void __launch_bounds__(256, 1) lstm_recur_kernel(
    const float* __restrict__ pre, const float* __restrict__ Whh,
    float* __restrict__ xout)
{
    constexpr int JS = H / G;       // units per CTA
    constexpr int KR = H / KH;      // k per slice
    constexpr int KQ = KR / 4;      // float4 quads per slice
    constexpr int KP = KR / 2;      // f32x2 pairs per gate
    constexpr int CELLS = NB * JS;  // (batch, unit) cells per CTA
    static_assert(JS * KH == 256, "map");
    static_assert(CELLS <= 256 * CPT, "cells");

    extern __shared__ float sm[];
    float* hs = sm;                        // [2][NB][H]
    ull*   red = (ull*)(hs + 2 * NB * H);  // [KH][NB][JS][4]

    const int tid = threadIdx.x;
    const int j   = tid % JS;
    const int kh  = tid / JS;
    const int grp = (G > 1) ? (blockIdx.x / G) : blockIdx.x;
    const int sl  = (G > 1) ? (blockIdx.x % G) : 0;
    const int b0  = grp * NB;
    const int j0  = sl * JS;

    // ---- load weight slice into registers (one-time) ----
    ull wr[4][KP];
#pragma unroll
    for (int g = 0; g < 4; g++) {
        const float4* wrow = reinterpret_cast<const float4*>(
            Whh + ((size_t)g * H + j0 + j) * H + kh * KR);
#pragma unroll
        for (int q = 0; q < KQ; q++) {
            float4 v = __ldg(wrow + q);
            wr[g][2 * q + 0] = pack2(v.x, v.y);
            wr[g][2 * q + 1] = pack2(v.z, v.w);
        }
    }

    for (int i = tid; i < 2 * NB * H; i += 256) hs[i] = 0.f;
    __syncthreads();
    if (G > 1) cluster_sync_();

    // ---- activation-cell identity ----
    const int cell0 = CPT * tid;
    const bool ACT = cell0 < CELLS;
    const int ab = ACT ? (cell0 / JS) : 0;   // batch (CPT cells share it)
    const int aj = ACT ? (cell0 % JS) : 0;   // first unit
    float c[CPT];
    float4 pin[CPT];
    const float4* pq = reinterpret_cast<const float4*>(
        pre + (size_t)(b0 + ab) * 4 * H + (size_t)(j0 + aj) * 4);
    float* xob = xout + (size_t)(b0 + ab) * H + (j0 + aj);
#pragma unroll
    for (int cc = 0; cc < CPT; cc++) {
        c[cc] = 0.f;
        if (ACT) pin[cc] = __ldcs(pq + cc);    // pre(t=0)
    }

    for (int t = 0; t < SEQ; t++) {
        const float* hcur = hs + (t & 1) * NB * H;

        // ---- dot: all NB batches over this thread's k-slice ----
#pragma unroll
        for (int b = 0; b < NB; b++) {
            const float4* hb = reinterpret_cast<const float4*>(hcur + b * H) + kh * KQ;
            ull a0 = 0ull, a1 = 0ull, a2 = 0ull, a3 = 0ull;
#pragma unroll
            for (int q = 0; q < KQ; q++) {
                float4 h4 = hb[q];
                const ull hp0 = pack2(h4.x, h4.y);
                const ull hp1 = pack2(h4.z, h4.w);
                ffma2(a0, hp0, wr[0][2 * q + 0]);
                ffma2(a1, hp0, wr[1][2 * q + 0]);
                ffma2(a2, hp0, wr[2][2 * q + 0]);
                ffma2(a3, hp0, wr[3][2 * q + 0]);
                ffma2(a0, hp1, wr[0][2 * q + 1]);
                ffma2(a1, hp1, wr[1][2 * q + 1]);
                ffma2(a2, hp1, wr[2][2 * q + 1]);
                ffma2(a3, hp1, wr[3][2 * q + 1]);
            }
            ull* rp = red + ((size_t)(kh * NB + b) * JS + j) * 4;
            rp[0] = a0; rp[1] = a1; rp[2] = a2; rp[3] = a3;
        }
        __syncthreads();

        // ---- reduce + activation ----
        float hv[CPT];
        if (ACT) {
#pragma unroll
            for (int cc = 0; cc < CPT; cc++) {
                const int jj = aj + cc;
                ull s0 = 0ull, s1 = 0ull, s2 = 0ull, s3 = 0ull;
#pragma unroll
                for (int kp = 0; kp < KH; kp++) {
                    const ull* rp = red + ((size_t)(kp * NB + ab) * JS + jj) * 4;
                    s0 = add2(s0, rp[0]); s1 = add2(s1, rp[1]);
                    s2 = add2(s2, rp[2]); s3 = add2(s3, rp[3]);
                }
                float l0, u0, l1, u1, l2, u2, l3, u3;
                unpk(s0, l0, u0); unpk(s1, l1, u1);
                unpk(s2, l2, u2); unpk(s3, l3, u3);
                const float gi = l0 + u0 + pin[cc].x;
                const float gf = l1 + u1 + pin[cc].y;
                const float gg = l2 + u2 + pin[cc].z;
                const float go = l3 + u3 + pin[cc].w;
                c[cc] = sigf(gf) * c[cc] + sigf(gi) * tanhfast(gg);
                hv[cc] = sigf(go) * tanhfast(c[cc]);
            }
            // write h(t+1) to own smem / all cluster peers
            float* hnx = hs + ((t + 1) & 1) * NB * H + ab * H + (j0 + aj);
            if (CPT == 2) {
                const ull hp = pack2(hv[0], hv[1]);
                if (G == 1) *reinterpret_cast<ull*>(hnx) = hp;
                else {
                    const uint32_t la = cvta_s(hnx);
#pragma unroll
                    for (unsigned d = 0; d < G; d++) stc64(la, d, hp);
                }
            } else {
                if (G == 1) hnx[0] = hv[0];
                else {
                    const uint32_t la = cvta_s(hnx);
#pragma unroll
                    for (unsigned d = 0; d < G; d++) stc32(la, d, hv[0]);
                }
            }
        }

        if (G > 1) cluster_arrive_();

        if (ACT) {
            // xout + pre(t+1) prefetch hidden under the barrier
            if (CPT == 2)
                *reinterpret_cast<float2*>(xob + (size_t)t * BATCH * H) =
                    make_float2(hv[0], hv[1]);
            else
                xob[(size_t)t * BATCH * H] = hv[0];
            const size_t toff = (size_t)((t + 1 < SEQ) ? t + 1 : t) * BATCH * H;
#pragma unroll
            for (int cc = 0; cc < CPT; cc++)
                pin[cc] = __ldcs(pq + toff + cc);
        }

        if (G > 1) cluster_wait_();
        else       __syncthreads();
    }
}

// ---------------- final linear (OUT_DIM=1) + tanh; x3 is [t][B][H2] -----------
__global__ void __launch_bounds__(256) final_kernel(
    const float* __restrict__ x3, const float* __restrict__ Wl,
    const float* __restrict__ bl, float* __restrict__ out)
{
    int m = (blockIdx.x * 256 + threadIdx.x) >> 5;   // m = t*B + b
    int lane = threadIdx.x & 31;
    const float* xr = x3 + (size_t)m * H2;
    float acc = 0.f;
#pragma unroll
    for (int i = 0; i < 8; i++) acc += xr[i * 32 + lane] * __ldg(&Wl[i * 32 + lane]);
#pragma unroll
    for (int off = 16; off; off >>= 1) acc += __shfl_xor_sync(0xffffffffu, acc, off);
    if (lane == 0) {
        const int t = m >> 8, b = m & 255;
        out[(size_t)b * SEQ + t] = tanhf(acc + bl[0]);
    }
}

// ---------------- launch ----------------
template <typename KernT>
static void launch_cluster(KernT kern, int grid, int G, int smem,
                           const float* pre, const float* Whh, float* xout)
{
    cudaLaunchConfig_t cfg = {};
    cfg.gridDim = dim3(grid, 1, 1);
    cfg.blockDim = dim3(256, 1, 1);
    cfg.dynamicSmemBytes = smem;
    cfg.stream = 0;
    cudaLaunchAttribute attr[1];
    attr[0].id = cudaLaunchAttributeClusterDimension;
    attr[0].val.clusterDim.x = G;
    attr[0].val.clusterDim.y = 1;
    attr[0].val.clusterDim.z = 1;
    cfg.attrs = attr;
    cfg.numAttrs = 1;
    cudaLaunchKernelEx(&cfg, kern, pre, Whh, xout);
}

extern "C" void kernel_launch(void* const* d_in, const int* in_sizes, int n_in,
                              void* d_out, int out_size)
{
    const float* noise = (const float*)d_in[0];
    const float* Wih0 = (const float*)d_in[1];
    const float* Whh0 = (const float*)d_in[2];
    const float* bih0 = (const float*)d_in[3];
    const float* bhh0 = (const float*)d_in[4];
    const float* Wih1 = (const float*)d_in[5];
    const float* Whh1 = (const float*)d_in[6];
    const float* bih1 = (const float*)d_in[7];
    const float* bhh1 = (const float*)d_in[8];
    const float* Wih2 = (const float*)d_in[9];
    const float* Whh2 = (const float*)d_in[10];
    const float* bih2 = (const float*)d_in[11];
    const float* bhh2 = (const float*)d_in[12];
    const float* Wl   = (const float*)d_in[13];
    const float* bl   = (const float*)d_in[14];
    float* out = (float*)d_out;

    float *pre, *x1, *x2, *x3;
    cudaGetSymbolAddress((void**)&pre, g_pre);
    cudaGetSymbolAddress((void**)&x1,  g_x1);
    cudaGetSymbolAddress((void**)&x2,  g_x2);
    cudaGetSymbolAddress((void**)&x3,  g_x3);

    // smem: hs[2][NB][H] f32 + red[KH][NB][JS][4] u64
    const int smem0 = 2 * 2 * H0 * 4   + 4 * 2 * 64 * 4 * 8;    //  17,408
    const int smem1 = 2 * 4 * H1 * 4   + 4 * 4 * 64 * 4 * 8;    //  36,864
    const int smem2 = 2 * 16 * H2 * 4  + 8 * 16 * 32 * 4 * 8;   // 163,840

    cudaFuncSetAttribute(lstm_recur_kernel<H0, 1, 2, 4, 1>,
                         cudaFuncAttributeMaxDynamicSharedMemorySize, smem0);
    cudaFuncSetAttribute(lstm_recur_kernel<H1, 2, 4, 4, 1>,
                         cudaFuncAttributeMaxDynamicSharedMemorySize, smem1);
    cudaFuncSetAttribute(lstm_recur_kernel<H2, 8, 16, 8, 2>,
                         cudaFuncAttributeMaxDynamicSharedMemorySize, smem2);

    const int MBLK = (BATCH * SEQ) / 128;

    gemm_pre_kernel<INDIM, 4 * H0, true><<<dim3(MBLK, (4 * H0) / 64), 256>>>(
        noise, Wih0, bih0, bhh0, pre);
    lstm_recur_kernel<H0, 1, 2, 4, 1><<<128, 256, smem0>>>(pre, Whh0, x1);

    gemm_pre_kernel<H0, 4 * H1, false><<<dim3(MBLK, (4 * H1) / 64), 256>>>(
        x1, Wih1, bih1, bhh1, pre);
    launch_cluster(lstm_recur_kernel<H1, 2, 4, 4, 1>, 128, 2, smem1, pre, Whh1, x2);

    gemm_pre_kernel<H1, 4 * H2, false><<<dim3(MBLK, (4 * H2) / 64), 256>>>(
        x2, Wih2, bih2, bhh2, pre);
    launch_cluster(lstm_recur_kernel<H2, 8, 16, 8, 2>, 128, 8, smem2, pre, Whh2, x3);

    final_kernel<<<(BATCH * SEQ) / 8, 256>>>(x3, Wl, bl, out);
}